// round 2
// baseline (speedup 1.0000x reference)
#include <cuda_runtime.h>
#include <math.h>

#define D_MODEL 512
#define N_HEADS 8
#define HD      64
#define BATCH   2
#define SEQ     4096
#define MROWS   (BATCH * SEQ)   // 8192

typedef unsigned long long u64;

// ---- packed fp32x2 helpers (sm_100+/sm_103a) -------------------------------
__device__ __forceinline__ u64 pk2(float lo, float hi) {
    u64 r; asm("mov.b64 %0, {%1, %2};" : "=l"(r) : "f"(lo), "f"(hi)); return r;
}
__device__ __forceinline__ u64 dup2(float v) { return pk2(v, v); }
__device__ __forceinline__ float2 up2(u64 v) {
    float2 r; asm("mov.b64 {%0, %1}, %2;" : "=f"(r.x), "=f"(r.y) : "l"(v)); return r;
}
__device__ __forceinline__ void fma2(u64& d, u64 a, u64 b) {
    asm("fma.rn.f32x2 %0, %1, %2, %0;" : "+l"(d) : "l"(a), "l"(b));
}
__device__ __forceinline__ void mul2(u64& d, u64 a, u64 b) {
    asm("mul.rn.f32x2 %0, %1, %2;" : "=l"(d) : "l"(a), "l"(b));
}

// Scratch
__device__ float g_QT[D_MODEL * MROWS];   // Q transposed: [n=512][m=8192]
__device__ float g_KT[D_MODEL * MROWS];   // K transposed: [n=512][m=8192]
__device__ float g_V [MROWS * D_MODEL];   // V natural
__device__ float g_attn[MROWS * D_MODEL]; // attn natural

// ---------------------------------------------------------------------------
// GEMM: C[M,N] = A[M,K] @ B[K,N] + bias ; M=8192, N=K=512
// Block 128x128, K-tile 16, 256 threads, 8x8 micro-tile, f32x2 FMA.
// Accumulators paired along M (natural pairs from As[k][m]).
// ---------------------------------------------------------------------------
__global__ __launch_bounds__(256) void gemm_kernel(
    const float* __restrict__ A, const float* __restrict__ B,
    const float* __restrict__ bias, float* __restrict__ C, int trans_out)
{
    const int M = MROWS, N = D_MODEL, K = D_MODEL;
    __shared__ float As[16][128];   // [k][m]
    __shared__ float Bs[16][128];   // [k][n]

    int tid = threadIdx.x;
    int tx = tid & 15, ty = tid >> 4;
    int bm = blockIdx.y * 128, bn = blockIdx.x * 128;

    int a_row = tid >> 1;           // 0..127
    int a_k0  = (tid & 1) * 8;      // 0 or 8

    u64 acc[4][8];
#pragma unroll
    for (int i = 0; i < 4; i++)
#pragma unroll
        for (int j = 0; j < 8; j++) acc[i][j] = 0ULL;

    const float* Aptr = A + (size_t)(bm + a_row) * K + a_k0;

    for (int kt = 0; kt < K; kt += 16) {
        float4 av0 = *(const float4*)(Aptr + kt);
        float4 av1 = *(const float4*)(Aptr + kt + 4);
        float4 bv[2];
#pragma unroll
        for (int i = 0; i < 2; i++) {
            int slot = tid + i * 256;
            int row = slot >> 5, c4 = slot & 31;
            bv[i] = *(const float4*)&B[(size_t)(kt + row) * N + bn + c4 * 4];
        }
        __syncthreads();
        As[a_k0 + 0][a_row] = av0.x;  As[a_k0 + 1][a_row] = av0.y;
        As[a_k0 + 2][a_row] = av0.z;  As[a_k0 + 3][a_row] = av0.w;
        As[a_k0 + 4][a_row] = av1.x;  As[a_k0 + 5][a_row] = av1.y;
        As[a_k0 + 6][a_row] = av1.z;  As[a_k0 + 7][a_row] = av1.w;
#pragma unroll
        for (int i = 0; i < 2; i++) {
            int slot = tid + i * 256;
            int row = slot >> 5, c4 = slot & 31;
            *(float4*)&Bs[row][c4 * 4] = bv[i];
        }
        __syncthreads();

#pragma unroll
        for (int k = 0; k < 16; k++) {
            ulonglong2 a01 = *(const ulonglong2*)&As[k][ty * 8];
            ulonglong2 a23 = *(const ulonglong2*)&As[k][ty * 8 + 4];
            u64 ap[4] = {a01.x, a01.y, a23.x, a23.y};
            float4 b0 = *(const float4*)&Bs[k][tx * 8];
            float4 b1 = *(const float4*)&Bs[k][tx * 8 + 4];
            u64 bd[8] = {dup2(b0.x), dup2(b0.y), dup2(b0.z), dup2(b0.w),
                         dup2(b1.x), dup2(b1.y), dup2(b1.z), dup2(b1.w)};
#pragma unroll
            for (int i = 0; i < 4; i++)
#pragma unroll
                for (int j = 0; j < 8; j++)
                    fma2(acc[i][j], ap[i], bd[j]);
        }
        __syncthreads();
    }

    if (!trans_out) {
        float4 bb0 = *(const float4*)&bias[bn + tx * 8];
        float4 bb1 = *(const float4*)&bias[bn + tx * 8 + 4];
        float bb[8] = {bb0.x, bb0.y, bb0.z, bb0.w, bb1.x, bb1.y, bb1.z, bb1.w};
#pragma unroll
        for (int r = 0; r < 8; r++) {
            int m = bm + ty * 8 + r;
            int ip = r >> 1, half = r & 1;
            float v[8];
#pragma unroll
            for (int j = 0; j < 8; j++) {
                float2 t = up2(acc[ip][j]);
                v[j] = (half ? t.y : t.x) + bb[j];
            }
            *(float4*)&C[(size_t)m * N + bn + tx * 8]     = make_float4(v[0], v[1], v[2], v[3]);
            *(float4*)&C[(size_t)m * N + bn + tx * 8 + 4] = make_float4(v[4], v[5], v[6], v[7]);
        }
    } else {
#pragma unroll
        for (int j = 0; j < 8; j++) {
            int n = bn + tx * 8 + j;
            float bj = bias[n];
            float2 t0 = up2(acc[0][j]);
            float2 t1 = up2(acc[1][j]);
            float2 t2 = up2(acc[2][j]);
            float2 t3 = up2(acc[3][j]);
            *(float4*)&C[(size_t)n * M + bm + ty * 8] =
                make_float4(t0.x + bj, t0.y + bj, t1.x + bj, t1.y + bj);
            *(float4*)&C[(size_t)n * M + bm + ty * 8 + 4] =
                make_float4(t2.x + bj, t2.y + bj, t3.x + bj, t3.y + bj);
        }
    }
}

// ---------------------------------------------------------------------------
// Flash attention (fp32, f32x2 FMA). Q-tile 128, K-tile 64, 256 threads.
// Per-thread: S micro 8q x 4k, O micro 8q x 4d, accumulators paired along q.
// ---------------------------------------------------------------------------
__global__ __launch_bounds__(256, 2) void flash_kernel(
    const float* __restrict__ QT, const float* __restrict__ KT,
    const float* __restrict__ V, float* __restrict__ O)
{
    extern __shared__ float sm[];
    float (*Qs)[128] = (float(*)[128])(sm);                       // [d][q] 64x128
    float (*Ks)[64]  = (float(*)[64])(sm + 64 * 128);             // [d][k] 64x64
    float (*Vs)[64]  = (float(*)[64])(sm + 64 * 128 + 64 * 64);   // [k][d] 64x64
    float (*Ps)[68]  = (float(*)[68])(sm + 64 * 128 + 2 * 64 * 64); // [q][k] 128x68

    const int M = MROWS;
    int b = blockIdx.z, h = blockIdx.y;
    int q0 = blockIdx.x * 128;
    int tid = threadIdx.x, tx = tid & 15, ty = tid >> 4;
    const float scale = 0.125f;

    // Load Q tile [d][q], scaled: 64x128 = 2048 float4 slots
#pragma unroll
    for (int i = 0; i < 8; i++) {
        int slot = tid + i * 256;
        int d = slot >> 5, q4 = slot & 31;
        float4 v = *(const float4*)&QT[(size_t)(h * HD + d) * M + b * SEQ + q0 + q4 * 4];
        v.x *= scale; v.y *= scale; v.z *= scale; v.w *= scale;
        *(float4*)&Qs[d][q4 * 4] = v;
    }

    u64 o[4][4];
    float mi[8], li[8];
#pragma unroll
    for (int i = 0; i < 4; i++)
#pragma unroll
        for (int j = 0; j < 4; j++) o[i][j] = 0ULL;
#pragma unroll
    for (int r = 0; r < 8; r++) { mi[r] = -1e30f; li[r] = 0.0f; }

    for (int j0 = 0; j0 < SEQ; j0 += 64) {
        __syncthreads();   // prev-iter PV done (and Q stores before first compute)
#pragma unroll
        for (int i = 0; i < 4; i++) {
            int slot = tid + i * 256;
            int r = slot >> 4, c4 = slot & 15;
            *(float4*)&Ks[r][c4 * 4] =
                *(const float4*)&KT[(size_t)(h * HD + r) * M + b * SEQ + j0 + c4 * 4];
            *(float4*)&Vs[r][c4 * 4] =
                *(const float4*)&V[(size_t)(b * SEQ + j0 + r) * D_MODEL + h * HD + c4 * 4];
        }
        __syncthreads();

        // S = Q^T K  (pairs along q)
        u64 s[4][4];
#pragma unroll
        for (int i = 0; i < 4; i++)
#pragma unroll
            for (int j = 0; j < 4; j++) s[i][j] = 0ULL;

#pragma unroll 8
        for (int d = 0; d < 64; d++) {
            ulonglong2 qa = *(const ulonglong2*)&Qs[d][ty * 8];
            ulonglong2 qb = *(const ulonglong2*)&Qs[d][ty * 8 + 4];
            u64 ap[4] = {qa.x, qa.y, qb.x, qb.y};
            float4 kv = *(const float4*)&Ks[d][tx * 4];
            u64 kd[4] = {dup2(kv.x), dup2(kv.y), dup2(kv.z), dup2(kv.w)};
#pragma unroll
            for (int i = 0; i < 4; i++)
#pragma unroll
                for (int j = 0; j < 4; j++)
                    fma2(s[i][j], ap[i], kd[j]);
        }

        // unpack scores
        float sf[8][4];
#pragma unroll
        for (int ip = 0; ip < 4; ip++)
#pragma unroll
            for (int j = 0; j < 4; j++) {
                float2 t = up2(s[ip][j]);
                sf[ip * 2][j] = t.x;
                sf[ip * 2 + 1][j] = t.y;
            }

        // online softmax (reduce over 16 tx lanes)
        float alpha[8];
#pragma unroll
        for (int r = 0; r < 8; r++) {
            float mx = fmaxf(fmaxf(sf[r][0], sf[r][1]), fmaxf(sf[r][2], sf[r][3]));
            mx = fmaxf(mx, __shfl_xor_sync(0xffffffffu, mx, 1));
            mx = fmaxf(mx, __shfl_xor_sync(0xffffffffu, mx, 2));
            mx = fmaxf(mx, __shfl_xor_sync(0xffffffffu, mx, 4));
            mx = fmaxf(mx, __shfl_xor_sync(0xffffffffu, mx, 8));
            float mn = fmaxf(mi[r], mx);
            alpha[r] = __expf(mi[r] - mn);
            mi[r] = mn;
            float rs = 0.0f;
#pragma unroll
            for (int j = 0; j < 4; j++) {
                float p = __expf(sf[r][j] - mn);
                sf[r][j] = p;
                rs += p;
            }
            rs += __shfl_xor_sync(0xffffffffu, rs, 1);
            rs += __shfl_xor_sync(0xffffffffu, rs, 2);
            rs += __shfl_xor_sync(0xffffffffu, rs, 4);
            rs += __shfl_xor_sync(0xffffffffu, rs, 8);
            li[r] = li[r] * alpha[r] + rs;
        }
#pragma unroll
        for (int ip = 0; ip < 4; ip++) {
            u64 ad = pk2(alpha[ip * 2], alpha[ip * 2 + 1]);
#pragma unroll
            for (int j = 0; j < 4; j++) mul2(o[ip][j], o[ip][j], ad);
        }

        // stage P rows
#pragma unroll
        for (int r = 0; r < 8; r++)
            *(float4*)&Ps[ty * 8 + r][tx * 4] =
                make_float4(sf[r][0], sf[r][1], sf[r][2], sf[r][3]);
        __syncthreads();

        // O += P V
#pragma unroll 4
        for (int k = 0; k < 64; k += 2) {
            float2 pr[8];
#pragma unroll
            for (int r = 0; r < 8; r++)
                pr[r] = *(const float2*)&Ps[ty * 8 + r][k];
#pragma unroll
            for (int kk = 0; kk < 2; kk++) {
                float4 vv = *(const float4*)&Vs[k + kk][tx * 4];
                u64 vd[4] = {dup2(vv.x), dup2(vv.y), dup2(vv.z), dup2(vv.w)};
                u64 pq[4];
#pragma unroll
                for (int ip = 0; ip < 4; ip++)
                    pq[ip] = kk ? pk2(pr[ip * 2].y, pr[ip * 2 + 1].y)
                                : pk2(pr[ip * 2].x, pr[ip * 2 + 1].x);
#pragma unroll
                for (int ip = 0; ip < 4; ip++)
#pragma unroll
                    for (int j = 0; j < 4; j++)
                        fma2(o[ip][j], pq[ip], vd[j]);
            }
        }
    }

    // normalize + store
#pragma unroll
    for (int r = 0; r < 8; r++) {
        float inv = 1.0f / li[r];
        int ip = r >> 1, half = r & 1;
        float v[4];
#pragma unroll
        for (int j = 0; j < 4; j++) {
            float2 t = up2(o[ip][j]);
            v[j] = (half ? t.y : t.x) * inv;
        }
        *(float4*)&O[(size_t)(b * SEQ + q0 + ty * 8 + r) * D_MODEL + h * HD + tx * 4] =
            make_float4(v[0], v[1], v[2], v[3]);
    }
}

// ---------------------------------------------------------------------------
extern "C" void kernel_launch(void* const* d_in, const int* in_sizes, int n_in,
                              void* d_out, int out_size)
{
    const float* x  = (const float*)d_in[0];
    const float* Wq = (const float*)d_in[1];
    const float* bq = (const float*)d_in[2];
    const float* Wk = (const float*)d_in[3];
    const float* bk = (const float*)d_in[4];
    const float* Wv = (const float*)d_in[5];
    const float* bv = (const float*)d_in[6];
    const float* Wo = (const float*)d_in[7];
    const float* bo = (const float*)d_in[8];
    float* out = (float*)d_out;

    float *QT, *KT, *Vb, *attn;
    cudaGetSymbolAddress((void**)&QT,   g_QT);
    cudaGetSymbolAddress((void**)&KT,   g_KT);
    cudaGetSymbolAddress((void**)&Vb,   g_V);
    cudaGetSymbolAddress((void**)&attn, g_attn);

    const int smem_flash = (64 * 128 + 2 * 64 * 64 + 128 * 68) * (int)sizeof(float); // 100352
    cudaFuncSetAttribute(flash_kernel,
                         cudaFuncAttributeMaxDynamicSharedMemorySize, smem_flash);

    dim3 ggrid(D_MODEL / 128, MROWS / 128);   // (4, 64)
    gemm_kernel<<<ggrid, 256>>>(x, Wq, bq, QT, 1);
    gemm_kernel<<<ggrid, 256>>>(x, Wk, bk, KT, 1);
    gemm_kernel<<<ggrid, 256>>>(x, Wv, bv, Vb, 0);

    dim3 fgrid(SEQ / 128, N_HEADS, BATCH);    // (32, 8, 2)
    flash_kernel<<<fgrid, 256, smem_flash>>>(QT, KT, Vb, attn);

    gemm_kernel<<<ggrid, 256>>>(attn, Wo, bo, out, 0);
}